// round 16
// baseline (speedup 1.0000x reference)
#include <cuda_runtime.h>
#include <cuda_fp16.h>
#include <cstdint>

#define NN 20000
#define BB 64
#define EE 1280000
#define CAP 192                  // slab capacity per node (Poisson(64); 16 sigma)

// Scratch (allocation-free -> __device__ globals)
__device__ __align__(16) __half g_xTh[NN * BB];      // x transposed, fp16 [N, B]
__device__ int g_cnt[NN];                            // zeroed in k_transpose
__device__ __align__(16) unsigned g_slab[NN * CAP];  // packed (src<<16 | fp16 coeff)

// ---------------------------------------------------------------------------
// K0: transpose x [B,N] -> xTh [N,B] (fp16); zero g_cnt. (R13-proven)
// ---------------------------------------------------------------------------
__global__ void __launch_bounds__(256) k_transpose(const float* __restrict__ x) {
    __shared__ float tile[32][33];
    const int n0 = (blockIdx.x >> 1) * 32;   // 625 n-tiles
    const int b0 = (blockIdx.x & 1) * 32;

    for (int i = blockIdx.x * 256 + threadIdx.x; i < NN; i += 1250 * 256)
        g_cnt[i] = 0;

    {
        const int bb = threadIdx.x >> 3;
        const int nv = (threadIdx.x & 7) * 4;
        float4 v = *(const float4*)(x + (size_t)(b0 + bb) * NN + n0 + nv);
        tile[nv + 0][bb] = v.x;
        tile[nv + 1][bb] = v.y;
        tile[nv + 2][bb] = v.z;
        tile[nv + 3][bb] = v.w;
    }
    __syncthreads();
    {
        const int nl = threadIdx.x >> 3;
        const int bv = (threadIdx.x & 7) * 4;
        __half2 h01 = __floats2half2_rn(tile[nl][bv + 0], tile[nl][bv + 1]);
        __half2 h23 = __floats2half2_rn(tile[nl][bv + 2], tile[nl][bv + 3]);
        uint2 u;
        u.x = *reinterpret_cast<unsigned*>(&h01);
        u.y = *reinterpret_cast<unsigned*>(&h23);
        *reinterpret_cast<uint2*>(g_xTh + (size_t)(n0 + nl) * 64 + b0 + bv) = u;
    }
}

// ---------------------------------------------------------------------------
// K1: slab scatter, 8 edges/thread, packed 4-byte records. (R15-proven)
// ---------------------------------------------------------------------------
__device__ __forceinline__ unsigned pack_rec(int s, float c) {
    return ((unsigned)s << 16) | (unsigned)__half_as_ushort(__float2half_rn(c));
}

__global__ void k_scatter(const float* __restrict__ adj,
                          const float* __restrict__ w,
                          const int* __restrict__ src,
                          const int* __restrict__ dst) {
    int t = blockIdx.x * 256 + threadIdx.x;      // < 160000 (EE/8)
    int4   s0 = __ldg(&((const int4*)src)[2 * t]);
    int4   s1 = __ldg(&((const int4*)src)[2 * t + 1]);
    int4   d0 = __ldg(&((const int4*)dst)[2 * t]);
    int4   d1 = __ldg(&((const int4*)dst)[2 * t + 1]);
    float4 a0 = __ldg(&((const float4*)adj)[2 * t]);
    float4 a1 = __ldg(&((const float4*)adj)[2 * t + 1]);
    float4 q0 = __ldg(&((const float4*)w)[2 * t]);
    float4 q1 = __ldg(&((const float4*)w)[2 * t + 1]);

    int p0 = atomicAdd(&g_cnt[d0.x], 1);
    int p1 = atomicAdd(&g_cnt[d0.y], 1);
    int p2 = atomicAdd(&g_cnt[d0.z], 1);
    int p3 = atomicAdd(&g_cnt[d0.w], 1);
    int p4 = atomicAdd(&g_cnt[d1.x], 1);
    int p5 = atomicAdd(&g_cnt[d1.y], 1);
    int p6 = atomicAdd(&g_cnt[d1.z], 1);
    int p7 = atomicAdd(&g_cnt[d1.w], 1);

    if (p0 < CAP) g_slab[(size_t)d0.x * CAP + p0] = pack_rec(s0.x, a0.x * q0.x);
    if (p1 < CAP) g_slab[(size_t)d0.y * CAP + p1] = pack_rec(s0.y, a0.y * q0.y);
    if (p2 < CAP) g_slab[(size_t)d0.z * CAP + p2] = pack_rec(s0.z, a0.z * q0.z);
    if (p3 < CAP) g_slab[(size_t)d0.w * CAP + p3] = pack_rec(s0.w, a0.w * q0.w);
    if (p4 < CAP) g_slab[(size_t)d1.x * CAP + p4] = pack_rec(s1.x, a1.x * q1.x);
    if (p5 < CAP) g_slab[(size_t)d1.y * CAP + p5] = pack_rec(s1.y, a1.y * q1.y);
    if (p6 < CAP) g_slab[(size_t)d1.z * CAP + p6] = pack_rec(s1.z, a1.z * q1.z);
    if (p7 < CAP) g_slab[(size_t)d1.w * CAP + p7] = pack_rec(s1.w, a1.w * q1.w);
}

// ---------------------------------------------------------------------------
// K2: 2 warps per node. 512 threads = 16 warps = 8 nodes x 2 warps.
// Warp j of a pair processes chunks f == j (mod 2); remainder owned by warp
// (nfull & 1). Inner loop identical to R15. Partials combined through smem;
// epilogue (x[0]*self_w scale + bias + relu) applied in the combine stage.
// ---------------------------------------------------------------------------
__global__ void __launch_bounds__(512) k_accum(const float* __restrict__ x,
                                               const float* __restrict__ self_w,
                                               const float* __restrict__ bias,
                                               float* __restrict__ out) {
    __shared__ float sacc[16][65];
    __shared__ float ssl[8], sbs[8];
    const int wp = threadIdx.x >> 5;   // 0..15
    const int lane = threadIdx.x & 31;
    const int q4 = lane >> 3;          // 0..3
    const int f8 = lane & 7;           // feature octet
    const int m = wp >> 1;             // node within block (0..7)
    const int j = wp & 1;              // half index
    const int n0 = blockIdx.x * 8;
    const int n = n0 + m;

    if (threadIdx.x < 8) {
        int nn = n0 + threadIdx.x;
        ssl[threadIdx.x] = __ldg(&x[nn]) * __ldg(&self_w[nn]);  // x row 0
        sbs[threadIdx.x] = __ldg(&bias[nn]);
    }

    const int cnt = min(__ldg(&g_cnt[n]), CAP);
    const int nfull = cnt >> 5;

    float acc0 = 0.f, acc1 = 0.f, acc2 = 0.f, acc3 = 0.f;
    float acc4 = 0.f, acc5 = 0.f, acc6 = 0.f, acc7 = 0.f;

    for (int f = j; f < nfull; f += 2) {
        unsigned r = g_slab[(size_t)n * CAP + f * 32 + lane];
        #pragma unroll
        for (int i = 0; i < 8; i++) {
            unsigned rec = __shfl_sync(0xffffffffu, r, 4 * i + q4);
            unsigned sv = rec >> 16;
            float c = __half2float(__ushort_as_half((unsigned short)(rec & 0xffffu)));
            uint4 hv = *(const uint4*)(g_xTh + (size_t)sv * 64 + f8 * 8);
            float2 f0 = __half22float2(*reinterpret_cast<__half2*>(&hv.x));
            float2 f1 = __half22float2(*reinterpret_cast<__half2*>(&hv.y));
            float2 f2 = __half22float2(*reinterpret_cast<__half2*>(&hv.z));
            float2 f3 = __half22float2(*reinterpret_cast<__half2*>(&hv.w));
            acc0 = fmaf(c, f0.x, acc0); acc1 = fmaf(c, f0.y, acc1);
            acc2 = fmaf(c, f1.x, acc2); acc3 = fmaf(c, f1.y, acc3);
            acc4 = fmaf(c, f2.x, acc4); acc5 = fmaf(c, f2.y, acc5);
            acc6 = fmaf(c, f3.x, acc6); acc7 = fmaf(c, f3.y, acc7);
        }
    }
    const int rem = cnt & 31;
    if (rem > 0 && j == (nfull & 1)) {
        const int base = n * CAP + nfull * 32;
        unsigned r = (lane < rem) ? g_slab[base + lane] : 0u;
        const int nquad = (rem + 3) >> 2;
        for (int i = 0; i < nquad; i++) {
            int idx = 4 * i + q4;
            unsigned rec = __shfl_sync(0xffffffffu, r, idx);
            unsigned sv = rec >> 16;
            float c = __half2float(__ushort_as_half((unsigned short)(rec & 0xffffu)));
            c = (idx < rem) ? c : 0.0f;
            uint4 hv = *(const uint4*)(g_xTh + (size_t)sv * 64 + f8 * 8);
            float2 f0 = __half22float2(*reinterpret_cast<__half2*>(&hv.x));
            float2 f1 = __half22float2(*reinterpret_cast<__half2*>(&hv.y));
            float2 f2 = __half22float2(*reinterpret_cast<__half2*>(&hv.z));
            float2 f3 = __half22float2(*reinterpret_cast<__half2*>(&hv.w));
            acc0 = fmaf(c, f0.x, acc0); acc1 = fmaf(c, f0.y, acc1);
            acc2 = fmaf(c, f1.x, acc2); acc3 = fmaf(c, f1.y, acc3);
            acc4 = fmaf(c, f2.x, acc4); acc5 = fmaf(c, f2.y, acc5);
            acc6 = fmaf(c, f3.x, acc6); acc7 = fmaf(c, f3.y, acc7);
        }
    }

    // Reduce the 4 quarter-warp partials (lanes differ only in q4).
    #pragma unroll
    for (int mm = 8; mm <= 16; mm <<= 1) {
        acc0 += __shfl_xor_sync(0xffffffffu, acc0, mm);
        acc1 += __shfl_xor_sync(0xffffffffu, acc1, mm);
        acc2 += __shfl_xor_sync(0xffffffffu, acc2, mm);
        acc3 += __shfl_xor_sync(0xffffffffu, acc3, mm);
        acc4 += __shfl_xor_sync(0xffffffffu, acc4, mm);
        acc5 += __shfl_xor_sync(0xffffffffu, acc5, mm);
        acc6 += __shfl_xor_sync(0xffffffffu, acc6, mm);
        acc7 += __shfl_xor_sync(0xffffffffu, acc7, mm);
    }

    if (q4 == 0) {
        float* sp = &sacc[wp][8 * f8];
        sp[0] = acc0; sp[1] = acc1; sp[2] = acc2; sp[3] = acc3;
        sp[4] = acc4; sp[5] = acc5; sp[6] = acc6; sp[7] = acc7;
    }
    __syncthreads();

    // Combine the 2 half-partials, apply epilogue, write out.
    // thread e: b = e>>3 (batch), i = e&7 (node). 8 consecutive n per 8
    // threads -> 32B coalesced segments.
    {
        int e = threadIdx.x;          // 0..511
        int b = e >> 3;
        int i = e & 7;
        float v = sacc[2 * i][b] + sacc[2 * i + 1][b];
        out[(size_t)b * NN + n0 + i] = fmaxf(fmaf(v, ssl[i], sbs[i]), 0.0f);
    }
}

// ---------------------------------------------------------------------------
// Launch. Inputs: x, adj_values, w, self_w, b, src, dst.
// ---------------------------------------------------------------------------
extern "C" void kernel_launch(void* const* d_in, const int* in_sizes, int n_in,
                              void* d_out, int out_size) {
    const float* x      = (const float*)d_in[0];
    const float* adj    = (const float*)d_in[1];
    const float* w      = (const float*)d_in[2];
    const float* self_w = (const float*)d_in[3];
    const float* bias   = (const float*)d_in[4];
    const int*   src    = (const int*)d_in[5];
    const int*   dst    = (const int*)d_in[6];
    float* out = (float*)d_out;

    k_transpose<<<1250, 256>>>(x);
    k_scatter<<<EE / 8 / 256, 256>>>(adj, w, src, dst);   // 625 blocks
    k_accum<<<NN / 8, 512>>>(x, self_w, bias, out);
}